// round 3
// baseline (speedup 1.0000x reference)
#include <cuda_runtime.h>
#include <cuda_bf16.h>
#include <math.h>

// ---------------------------------------------------------------------------
// MPNN on GB300, fused-layer version.
//  - CSR-by-destination rebuilt each call (deg atomics -> 1-block scan -> fill).
//  - k_layer: one block = 64 nodes. Phase A: gather neighbor sums into smem +
//    load own cur/eemb rows + load Wmsg. Phase B: GEMM1 (fma.rn.f32x2), relu'd
//    msg written to the GEMM2 smem tile. Phase C: reload Wupd, GEMM2 -> cout.
//  - k_edge: fused gather(h) + K=64 GEMM for the edge embedding.
//  - Readout pooled branch collapses to one scalar per graph.
// ---------------------------------------------------------------------------

#define MAXN 65536
#define MAXE 1048576
#define MAXG 512
#define FD   64

__device__ int   g_deg[MAXN];
__device__ int   g_rowptr[MAXN];
__device__ int   g_wptr[MAXN];
__device__ int   g_srcidx[MAXE];
__device__ float g_dinv[MAXN];
__device__ int   g_degmax;

__device__ float g_h[MAXN * FD];
__device__ float g_eemb[MAXN * FD];
__device__ float g_curA[MAXN * FD];
__device__ float g_curB[MAXN * FD];

__device__ float g_means[MAXG * FD];
__device__ float g_cnt[MAXG];
__device__ float g_gconst[MAXG];

// ---------------------------------------------------------------------------
__global__ void k_zero(int n) {
    int i = blockIdx.x * blockDim.x + threadIdx.x;
    int stride = gridDim.x * blockDim.x;
    for (int t = i; t < n; t += stride) g_deg[t] = 0;
    for (int t = i; t < MAXG * FD; t += stride) g_means[t] = 0.f;
    for (int t = i; t < MAXG; t += stride) g_cnt[t] = 0.f;
    if (i == 0) g_degmax = 0;
}

__global__ void k_deg(const int* __restrict__ col, int E) {
    int i = blockIdx.x * blockDim.x + threadIdx.x;
    if (i < E) atomicAdd(&g_deg[col[i]], 1);
}

// single-block exclusive scan over deg -> rowptr/wptr, plus dinv and degmax
__global__ void k_scan(int n) {
    __shared__ int sums[1024];
    __shared__ int smax[1024];
    int t = threadIdx.x;
    int chunk = (n + 1023) >> 10;
    int s = t * chunk;
    int e = min(s + chunk, n);
    int loc = 0, mx = 0;
    for (int i = s; i < e; i++) { int d = g_deg[i]; loc += d; mx = max(mx, d); }
    sums[t] = loc;
    smax[t] = mx;
    __syncthreads();
    for (int off = 1; off < 1024; off <<= 1) {
        int v = (t >= off) ? sums[t - off] : 0;
        __syncthreads();
        sums[t] += v;
        __syncthreads();
    }
    int run = (t == 0) ? 0 : sums[t - 1];
    for (int i = s; i < e; i++) {
        int d = g_deg[i];
        g_rowptr[i] = run;
        g_wptr[i]   = run;
        g_dinv[i]   = (d > 0) ? (1.0f / (float)d) : 0.0f;
        run += d;
    }
    for (int off = 512; off > 0; off >>= 1) {
        if (t < off) smax[t] = max(smax[t], smax[t + off]);
        __syncthreads();
    }
    if (t == 0) g_degmax = max(smax[0], 1);
}

__global__ void k_fill(const int* __restrict__ row, const int* __restrict__ col, int E) {
    int i = blockIdx.x * blockDim.x + threadIdx.x;
    if (i < E) {
        int p = atomicAdd(&g_wptr[col[i]], 1);
        g_srcidx[p] = row[i];
    }
}

// cur = relu(x @ W_init) ; h = relu(x @ W_e1) padded with 0 in col 63
__global__ void k_init(const float* __restrict__ x, const float* __restrict__ Wi,
                       const float* __restrict__ We1, int n, int nobs) {
    int t = blockIdx.x * blockDim.x + threadIdx.x;
    if (t >= n * 64) return;
    int node = t >> 6, c = t & 63;
    const float* xr = x + node * nobs;
    float s1 = 0.f, s2 = 0.f;
    for (int j = 0; j < nobs; j++) {
        float xv = __ldg(&xr[j]);
        s1 += xv * __ldg(&Wi[j * 64 + c]);
        if (c < 63) s2 += xv * __ldg(&We1[j * 63 + c]);
    }
    g_curA[t] = fmaxf(s1, 0.f);
    g_h[t]    = (c < 63) ? fmaxf(s2, 0.f) : 0.f;
}

// device helper: gather neighbor mean of feat[] for 64 nodes into smem tile.
// 256 threads = 16 half-warps; each half-warp does 4 nodes; lane = float4 slice.
__device__ __forceinline__ void gather_tile(const float* __restrict__ feat,
                                            float* __restrict__ dst, int pitch,
                                            int node0, int n, int degcol) {
    int hw = threadIdx.x >> 4;        // 0..15
    int lane = threadIdx.x & 15;      // float4 slice
    const float4* f4 = (const float4*)feat;
    for (int u = 0; u < 4; u++) {
        int nl = hw * 4 + u;          // local node 0..63
        int node = node0 + nl;
        if (node >= n) break;
        int start = g_rowptr[node];
        int d = g_deg[node];
        float ax = 0.f, ay = 0.f, az = 0.f, aw = 0.f;
        int i = 0;
        for (; i + 4 <= d; i += 4) {
            int s0 = __ldg(&g_srcidx[start + i]);
            int s1 = __ldg(&g_srcidx[start + i + 1]);
            int s2 = __ldg(&g_srcidx[start + i + 2]);
            int s3 = __ldg(&g_srcidx[start + i + 3]);
            float4 v0 = __ldg(&f4[s0 * 16 + lane]);
            float4 v1 = __ldg(&f4[s1 * 16 + lane]);
            float4 v2 = __ldg(&f4[s2 * 16 + lane]);
            float4 v3 = __ldg(&f4[s3 * 16 + lane]);
            ax += (v0.x + v1.x) + (v2.x + v3.x);
            ay += (v0.y + v1.y) + (v2.y + v3.y);
            az += (v0.z + v1.z) + (v2.z + v3.z);
            aw += (v0.w + v1.w) + (v2.w + v3.w);
        }
        for (; i < d; i++) {
            int s = __ldg(&g_srcidx[start + i]);
            float4 v = __ldg(&f4[s * 16 + lane]);
            ax += v.x; ay += v.y; az += v.z; aw += v.w;
        }
        float sc = g_dinv[node];
        ax *= sc; ay *= sc; az *= sc; aw *= sc;
        if (degcol && lane == 15) aw = (float)d / (float)g_degmax;
        *(float4*)&dst[nl * pitch + lane * 4] = make_float4(ax, ay, az, aw);
    }
}

// device helper: GEMM core. ins tile [64][PITCH] (K valid cols), Ws [K][64].
// thread (r=tid>>2, q=tid&3) computes row r, col groups {g*16+q*4}, g=0..3.
template <int K, int PITCH>
__device__ __forceinline__ void gemm_core(const float* __restrict__ ins,
                                          const float* __restrict__ Ws,
                                          unsigned long long acc[8]) {
    int r = threadIdx.x >> 2;
    int q = threadIdx.x & 3;
#pragma unroll
    for (int j = 0; j < 8; j++) acc[j] = 0ull;
    const float* insr = &ins[r * PITCH];
#pragma unroll 2
    for (int k = 0; k < K; k += 4) {
        float4 a = *(const float4*)&insr[k];
#pragma unroll
        for (int kk = 0; kk < 4; kk++) {
            float av = (kk == 0) ? a.x : (kk == 1) ? a.y : (kk == 2) ? a.z : a.w;
            unsigned long long av2;
            asm("mov.b64 %0, {%1, %1};" : "=l"(av2) : "f"(av));
            const float* wrow = &Ws[(k + kk) * 64 + q * 4];
#pragma unroll
            for (int g = 0; g < 4; g++) {
                ulonglong2 w = *(const ulonglong2*)&wrow[g * 16];
                asm("fma.rn.f32x2 %0, %1, %2, %0;" : "+l"(acc[g * 2])     : "l"(av2), "l"(w.x));
                asm("fma.rn.f32x2 %0, %1, %2, %0;" : "+l"(acc[g * 2 + 1]) : "l"(av2), "l"(w.y));
            }
        }
    }
}

__device__ __forceinline__ float4 acc_relu4(unsigned long long a0, unsigned long long a1) {
    float lo0, hi0, lo1, hi1;
    asm("mov.b64 {%0, %1}, %2;" : "=f"(lo0), "=f"(hi0) : "l"(a0));
    asm("mov.b64 {%0, %1}, %2;" : "=f"(lo1), "=f"(hi1) : "l"(a1));
    float4 o;
    o.x = fmaxf(lo0, 0.f); o.y = fmaxf(hi0, 0.f);
    o.z = fmaxf(lo1, 0.f); o.w = fmaxf(hi1, 0.f);
    return o;
}

// Fused MPNN layer: gather(cur) | load eemb,cur rows | GEMM1(Wmsg) -> smem msg |
// GEMM2(Wupd) -> cout.  smem: Ws[128*64] + ins1[64*132] + ins2[64*132]
__global__ __launch_bounds__(256) void k_layer(const float* __restrict__ cur,
                                               const float* __restrict__ eemb,
                                               const float* __restrict__ Wmsg,
                                               const float* __restrict__ Wupd,
                                               float* __restrict__ cout, int n) {
    extern __shared__ float sm[];
    const int PITCH = 132;
    float* Ws   = sm;                    // 128*64
    float* ins1 = sm + 128 * 64;         // [nagg | eemb]
    float* ins2 = ins1 + 64 * PITCH;     // [cur  | msg ]
    int tid = threadIdx.x;
    int node0 = blockIdx.x * 64;

    // phase A: W, row tiles, gather
    for (int idx = tid; idx < 128 * 16; idx += 256)
        ((float4*)Ws)[idx] = __ldg((const float4*)Wmsg + idx);
    for (int idx = tid; idx < 1024; idx += 256) {
        int r = idx >> 4, c4 = (idx & 15) << 2;
        int node = node0 + r;
        float4 ve = make_float4(0.f, 0.f, 0.f, 0.f), vc = ve;
        if (node < n) {
            ve = __ldg((const float4*)&eemb[(size_t)node * 64 + c4]);
            vc = __ldg((const float4*)&cur[(size_t)node * 64 + c4]);
        }
        *(float4*)&ins1[r * PITCH + 64 + c4] = ve;
        *(float4*)&ins2[r * PITCH + c4]      = vc;
    }
    gather_tile(cur, ins1, PITCH, node0, n, 0);
    __syncthreads();

    // phase B: GEMM1 -> relu -> msg into ins2 cols 64..127
    {
        unsigned long long acc[8];
        gemm_core<128, PITCH>(ins1, Ws, acc);
        int r = tid >> 2, q = tid & 3;
        float* dst = &ins2[r * PITCH + 64 + q * 4];
#pragma unroll
        for (int g = 0; g < 4; g++)
            *(float4*)&dst[g * 16] = acc_relu4(acc[g * 2], acc[g * 2 + 1]);
    }
    __syncthreads();

    // reload W with Wupd
    for (int idx = tid; idx < 128 * 16; idx += 256)
        ((float4*)Ws)[idx] = __ldg((const float4*)Wupd + idx);
    __syncthreads();

    // phase C: GEMM2 -> relu -> cout
    {
        unsigned long long acc[8];
        gemm_core<128, PITCH>(ins2, Ws, acc);
        int r = tid >> 2, q = tid & 3;
        if (node0 + r < n) {
            float* Cr = &cout[(size_t)(node0 + r) * 64 + q * 4];
#pragma unroll
            for (int g = 0; g < 4; g++)
                *(float4*)&Cr[g * 16] = acc_relu4(acc[g * 2], acc[g * 2 + 1]);
        }
    }
}

// Fused edge embedding: gather(h) with deg column, then K=64 GEMM (We2) -> eemb
__global__ __launch_bounds__(256) void k_edge(const float* __restrict__ h,
                                              const float* __restrict__ We2,
                                              float* __restrict__ eemb, int n) {
    extern __shared__ float sm[];
    const int PITCH = 68;
    float* Ws  = sm;              // 64*64
    float* ins = sm + 64 * 64;    // 64*68
    int tid = threadIdx.x;
    int node0 = blockIdx.x * 64;

    for (int idx = tid; idx < 64 * 16; idx += 256)
        ((float4*)Ws)[idx] = __ldg((const float4*)We2 + idx);
    gather_tile(h, ins, PITCH, node0, n, 1);
    __syncthreads();

    unsigned long long acc[8];
    gemm_core<64, PITCH>(ins, Ws, acc);
    int r = tid >> 2, q = tid & 3;
    if (node0 + r < n) {
        float* Cr = &eemb[(size_t)(node0 + r) * 64 + q * 4];
#pragma unroll
        for (int g = 0; g < 4; g++)
            *(float4*)&Cr[g * 16] = acc_relu4(acc[g * 2], acc[g * 2 + 1]);
    }
}

// per-graph feature sums + counts (local run-length accumulation, then atomic)
__global__ void k_means(const float* __restrict__ cur, const int* __restrict__ batch, int n) {
    const int RPT = 16;
    int t = blockIdx.x * blockDim.x + threadIdx.x;
    int c  = t & 63;
    int rg = t >> 6;
    int n0 = rg * RPT;
    if (n0 >= n) return;
    int curb = __ldg(&batch[n0]);
    float acc = 0.f;
    float cnt = 0.f;
    for (int i = 0; i < RPT && n0 + i < n; i++) {
        int b = __ldg(&batch[n0 + i]);
        if (b != curb) {
            atomicAdd(&g_means[curb * 64 + c], acc);
            if (c == 0) atomicAdd(&g_cnt[curb], cnt);
            acc = 0.f; cnt = 0.f; curb = b;
        }
        acc += cur[(size_t)(n0 + i) * 64 + c];
        cnt += 1.f;
    }
    atomicAdd(&g_means[curb * 64 + c], acc);
    if (c == 0) atomicAdd(&g_cnt[curb], cnt);
}

// gconst[g] = relu(mean_g @ W_pool) . W_read[:64] + b_read
__global__ void k_gconst(const float* __restrict__ Wp, const float* __restrict__ Wr,
                         const float* __restrict__ br) {
    int g = blockIdx.x;
    int t = threadIdx.x;  // 64 threads
    __shared__ float m[64];
    __shared__ float red[64];
    float cnt = g_cnt[g];
    if (cnt <= 0.f) { if (t == 0) g_gconst[g] = 0.f; return; }
    m[t] = g_means[g * 64 + t] / cnt;
    __syncthreads();
    float p = 0.f;
#pragma unroll 8
    for (int k = 0; k < 64; k++) p += m[k] * __ldg(&Wp[k * 64 + t]);
    red[t] = fmaxf(p, 0.f) * __ldg(&Wr[t]);
    __syncthreads();
    if (t < 32) {
        float s = red[t] + red[t + 32];
#pragma unroll
        for (int off = 16; off > 0; off >>= 1) s += __shfl_down_sync(0xffffffffu, s, off);
        if (t == 0) g_gconst[g] = s + __ldg(&br[0]);
    }
}

// out[n] = gconst[batch[n]] + relu(cur[n]) . W_read[64:]
__global__ void k_out(const float* __restrict__ cur, const int* __restrict__ batch,
                      const float* __restrict__ Wr, float* __restrict__ out, int n) {
    int w = (blockIdx.x * blockDim.x + threadIdx.x) >> 5;
    int lane = threadIdx.x & 31;
    if (w >= n) return;
    float f1 = cur[(size_t)w * 64 + lane];
    float f2 = cur[(size_t)w * 64 + 32 + lane];
    float s = fmaxf(f1, 0.f) * __ldg(&Wr[64 + lane]) + fmaxf(f2, 0.f) * __ldg(&Wr[96 + lane]);
#pragma unroll
    for (int off = 16; off > 0; off >>= 1) s += __shfl_down_sync(0xffffffffu, s, off);
    if (lane == 0) out[w] = s + g_gconst[__ldg(&batch[w])];
}

// ---------------------------------------------------------------------------
extern "C" void kernel_launch(void* const* d_in, const int* in_sizes, int n_in,
                              void* d_out, int out_size) {
    const float* x    = (const float*)d_in[0];
    const float* Wi   = (const float*)d_in[1];
    const float* We1  = (const float*)d_in[2];
    const float* We2  = (const float*)d_in[3];
    const float* Wmsg = (const float*)d_in[4];
    const float* Wupd = (const float*)d_in[5];
    const float* Wp   = (const float*)d_in[6];
    const float* Wr   = (const float*)d_in[7];
    const float* br   = (const float*)d_in[8];
    const int*   eidx = (const int*)d_in[9];
    const int*   batch= (const int*)d_in[10];

    int n    = in_sizes[10];
    int E    = in_sizes[9] / 2;
    int nobs = in_sizes[0] / n;
    int L    = in_sizes[4] / (128 * 64);
    const int* row = eidx;
    const int* col = eidx + E;
    float* out = (float*)d_out;

    float *curA, *curB, *hbuf, *eemb;
    cudaGetSymbolAddress((void**)&curA, g_curA);
    cudaGetSymbolAddress((void**)&curB, g_curB);
    cudaGetSymbolAddress((void**)&hbuf, g_h);
    cudaGetSymbolAddress((void**)&eemb, g_eemb);

    const int SMEM_LAYER = (128 * 64 + 2 * 64 * 132) * 4;  // 100352
    const int SMEM_EDGE  = (64 * 64 + 64 * 68) * 4;        // 33792
    cudaFuncSetAttribute(k_layer, cudaFuncAttributeMaxDynamicSharedMemorySize, SMEM_LAYER);
    cudaFuncSetAttribute(k_edge,  cudaFuncAttributeMaxDynamicSharedMemorySize, SMEM_EDGE);

    int gE  = (E + 255) / 256;
    int gNF = (n * 64 + 255) / 256;
    int gW  = (n * 32 + 255) / 256;
    int gG  = (n + 63) / 64;
    int gM  = ((((n + 15) / 16) * 64) + 255) / 256;

    k_zero<<<256, 256>>>(n);
    k_deg<<<gE, 256>>>(col, E);
    k_scan<<<1, 1024>>>(n);
    k_fill<<<gE, 256>>>(row, col, E);
    k_init<<<gNF, 256>>>(x, Wi, We1, n, nobs);

    k_edge<<<gG, 256, SMEM_EDGE>>>(hbuf, We2, eemb, n);

    float* cin = curA;
    float* cout = curB;
    for (int l = 0; l < L; l++) {
        k_layer<<<gG, 256, SMEM_LAYER>>>(cin, eemb,
                                         Wmsg + (size_t)l * 8192,
                                         Wupd + (size_t)l * 8192, cout, n);
        float* tmp = cin; cin = cout; cout = tmp;
    }

    k_means<<<gM, 256>>>(cin, batch, n);
    k_gconst<<<MAXG, 64>>>(Wp, Wr, br);
    k_out<<<gW, 256>>>(cin, batch, Wr, out, n);
}

// round 4
// speedup vs baseline: 1.3065x; 1.3065x over previous
#include <cuda_runtime.h>
#include <cuda_bf16.h>
#include <math.h>

// ---------------------------------------------------------------------------
// MPNN on GB300 (round 4).
//  - Round-2 pipeline (separate gather / GEMM kernels — fusion regressed).
//  - GEMMs: 128 nodes/block, 2 rows/thread, fma.rn.f32x2, conflict-free W map.
//  - Last GEMM2 fuses the readout: per-node dot with W_read[64:] -> out[],
//    per-graph segmented mean sums -> g_means/g_cnt. Then k_gconst + k_addg.
//  - k_zero replaced by cudaMemsetAsync nodes.
// ---------------------------------------------------------------------------

#define MAXN 65536
#define MAXE 1048576
#define MAXG 512
#define FD   64

typedef unsigned long long ull;

__device__ int   g_deg[MAXN];
__device__ int   g_rowptr[MAXN];
__device__ int   g_wptr[MAXN];
__device__ int   g_srcidx[MAXE];
__device__ float g_dinv[MAXN];
__device__ int   g_degmax;

__device__ float g_h[MAXN * FD];
__device__ float g_nagg[MAXN * FD];
__device__ float g_msg[MAXN * FD];
__device__ float g_eemb[MAXN * FD];
__device__ float g_curA[MAXN * FD];
__device__ float g_curB[MAXN * FD];

__device__ float g_means[MAXG * FD];
__device__ float g_cnt[MAXG];
__device__ float g_gconst[MAXG];

// ---------------------------------------------------------------------------
__global__ void k_deg(const int* __restrict__ col, int E) {
    int i = blockIdx.x * blockDim.x + threadIdx.x;
    if (i < E) atomicAdd(&g_deg[col[i]], 1);
}

// single-block exclusive scan over deg -> rowptr/wptr, plus dinv and degmax
__global__ void k_scan(int n) {
    __shared__ int sums[1024];
    __shared__ int smax[1024];
    int t = threadIdx.x;
    int chunk = (n + 1023) >> 10;
    int s = t * chunk;
    int e = min(s + chunk, n);
    int loc = 0, mx = 0;
    for (int i = s; i < e; i++) { int d = g_deg[i]; loc += d; mx = max(mx, d); }
    sums[t] = loc;
    smax[t] = mx;
    __syncthreads();
    for (int off = 1; off < 1024; off <<= 1) {
        int v = (t >= off) ? sums[t - off] : 0;
        __syncthreads();
        sums[t] += v;
        __syncthreads();
    }
    int run = (t == 0) ? 0 : sums[t - 1];
    for (int i = s; i < e; i++) {
        int d = g_deg[i];
        g_rowptr[i] = run;
        g_wptr[i]   = run;
        g_dinv[i]   = (d > 0) ? (1.0f / (float)d) : 0.0f;
        run += d;
    }
    for (int off = 512; off > 0; off >>= 1) {
        if (t < off) smax[t] = max(smax[t], smax[t + off]);
        __syncthreads();
    }
    if (t == 0) g_degmax = max(smax[0], 1);
}

__global__ void k_fill(const int* __restrict__ row, const int* __restrict__ col, int E) {
    int i = blockIdx.x * blockDim.x + threadIdx.x;
    if (i < E) {
        int p = atomicAdd(&g_wptr[col[i]], 1);
        g_srcidx[p] = row[i];
    }
}

// cur = relu(x @ W_init) ; h = relu(x @ W_e1) padded with 0 in col 63
__global__ void k_init(const float* __restrict__ x, const float* __restrict__ Wi,
                       const float* __restrict__ We1, int n, int nobs) {
    int t = blockIdx.x * blockDim.x + threadIdx.x;
    if (t >= n * 64) return;
    int node = t >> 6, c = t & 63;
    const float* xr = x + node * nobs;
    float s1 = 0.f, s2 = 0.f;
    for (int j = 0; j < nobs; j++) {
        float xv = __ldg(&xr[j]);
        s1 += xv * __ldg(&Wi[j * 64 + c]);
        if (c < 63) s2 += xv * __ldg(&We1[j * 63 + c]);
    }
    g_curA[t] = fmaxf(s1, 0.f);
    g_h[t]    = (c < 63) ? fmaxf(s2, 0.f) : 0.f;
}

// pull-gather: half-warp per destination node, float4 per lane (16 lanes x 16B)
__global__ void k_gather(const float* __restrict__ feat, float* __restrict__ out,
                         int n, int degcol) {
    int hw = (blockIdx.x * blockDim.x + threadIdx.x) >> 4;
    int lane = threadIdx.x & 15;
    if (hw >= n) return;
    int start = g_rowptr[hw];
    int d = g_deg[hw];
    const float4* f4 = (const float4*)feat;
    float ax = 0.f, ay = 0.f, az = 0.f, aw = 0.f;
    int i = 0;
    for (; i + 4 <= d; i += 4) {
        int s0 = __ldg(&g_srcidx[start + i]);
        int s1 = __ldg(&g_srcidx[start + i + 1]);
        int s2 = __ldg(&g_srcidx[start + i + 2]);
        int s3 = __ldg(&g_srcidx[start + i + 3]);
        float4 v0 = __ldg(&f4[s0 * 16 + lane]);
        float4 v1 = __ldg(&f4[s1 * 16 + lane]);
        float4 v2 = __ldg(&f4[s2 * 16 + lane]);
        float4 v3 = __ldg(&f4[s3 * 16 + lane]);
        ax += (v0.x + v1.x) + (v2.x + v3.x);
        ay += (v0.y + v1.y) + (v2.y + v3.y);
        az += (v0.z + v1.z) + (v2.z + v3.z);
        aw += (v0.w + v1.w) + (v2.w + v3.w);
    }
    for (; i < d; i++) {
        int s = __ldg(&g_srcidx[start + i]);
        float4 v = __ldg(&f4[s * 16 + lane]);
        ax += v.x; ay += v.y; az += v.z; aw += v.w;
    }
    float sc = g_dinv[hw];
    ax *= sc; ay *= sc; az *= sc; aw *= sc;
    if (degcol && lane == 15) aw = (float)d / (float)g_degmax;
    ((float4*)out)[hw * 16 + lane] = make_float4(ax, ay, az, aw);
}

// ---------------------------------------------------------------------------
// GEMM core: 2 rows per thread (rr and rr+64), 16 cols per thread in 4 groups.
template <int K, int PITCH>
__device__ __forceinline__ void gemm_core2(const float* __restrict__ ins,
                                           const float* __restrict__ Ws,
                                           ull accA[8], ull accB[8]) {
    int rr = threadIdx.x >> 2;
    int q  = threadIdx.x & 3;
#pragma unroll
    for (int j = 0; j < 8; j++) { accA[j] = 0ull; accB[j] = 0ull; }
    const float* r0 = &ins[rr * PITCH];
    const float* r1 = &ins[(rr + 64) * PITCH];
#pragma unroll 2
    for (int k = 0; k < K; k += 4) {
        float4 a0 = *(const float4*)&r0[k];
        float4 a1 = *(const float4*)&r1[k];
#pragma unroll
        for (int kk = 0; kk < 4; kk++) {
            float av0 = (kk == 0) ? a0.x : (kk == 1) ? a0.y : (kk == 2) ? a0.z : a0.w;
            float av1 = (kk == 0) ? a1.x : (kk == 1) ? a1.y : (kk == 2) ? a1.z : a1.w;
            ull p0, p1;
            asm("mov.b64 %0, {%1, %1};" : "=l"(p0) : "f"(av0));
            asm("mov.b64 %0, {%1, %1};" : "=l"(p1) : "f"(av1));
            const float* wrow = &Ws[(k + kk) * 64 + q * 4];
#pragma unroll
            for (int g = 0; g < 4; g++) {
                ulonglong2 w = *(const ulonglong2*)&wrow[g * 16];
                asm("fma.rn.f32x2 %0, %1, %2, %0;" : "+l"(accA[g * 2])     : "l"(p0), "l"(w.x));
                asm("fma.rn.f32x2 %0, %1, %2, %0;" : "+l"(accA[g * 2 + 1]) : "l"(p0), "l"(w.y));
                asm("fma.rn.f32x2 %0, %1, %2, %0;" : "+l"(accB[g * 2])     : "l"(p1), "l"(w.x));
                asm("fma.rn.f32x2 %0, %1, %2, %0;" : "+l"(accB[g * 2 + 1]) : "l"(p1), "l"(w.y));
            }
        }
    }
}

__device__ __forceinline__ float4 acc_relu4(ull a0, ull a1) {
    float lo0, hi0, lo1, hi1;
    asm("mov.b64 {%0, %1}, %2;" : "=f"(lo0), "=f"(hi0) : "l"(a0));
    asm("mov.b64 {%0, %1}, %2;" : "=f"(lo1), "=f"(hi1) : "l"(a1));
    float4 o;
    o.x = fmaxf(lo0, 0.f); o.y = fmaxf(hi0, 0.f);
    o.z = fmaxf(lo1, 0.f); o.w = fmaxf(hi1, 0.f);
    return o;
}

// C[n,64] = relu( concat(A[n,64], B[n,64]) @ W[128,64] ).  128 nodes / block.
// If LAST: skip C; instead out[node] = relu(...).W_read[64:], and per-graph
// segmented sums of relu(...) into g_means / g_cnt.
template <bool LAST>
__global__ __launch_bounds__(256) void k_gemm128(const float* __restrict__ A,
                                                 const float* __restrict__ B,
                                                 const float* __restrict__ W,
                                                 float* __restrict__ C,
                                                 const float* __restrict__ Wr,
                                                 const int* __restrict__ batch,
                                                 float* __restrict__ out, int n) {
    extern __shared__ float sm[];
    const int PITCH = 132;
    float* Ws  = sm;                 // 128*64
    float* ins = sm + 128 * 64;      // 128*PITCH
    __shared__ float Wrs[64];
    int tid = threadIdx.x;
    int node0 = blockIdx.x * 128;

    for (int idx = tid; idx < 128 * 16; idx += 256)
        ((float4*)Ws)[idx] = __ldg((const float4*)W + idx);
    if (LAST && tid < 64) Wrs[tid] = __ldg(&Wr[64 + tid]);

    for (int idx = tid; idx < 2048; idx += 256) {
        int r = idx >> 4, c4 = (idx & 15) << 2;
        int node = node0 + r;
        float4 va = make_float4(0.f, 0.f, 0.f, 0.f), vb = va;
        if (node < n) {
            va = __ldg((const float4*)&A[(size_t)node * 64 + c4]);
            vb = __ldg((const float4*)&B[(size_t)node * 64 + c4]);
        }
        *(float4*)&ins[r * PITCH + c4]      = va;
        *(float4*)&ins[r * PITCH + 64 + c4] = vb;
    }
    __syncthreads();

    ull accA[8], accB[8];
    gemm_core2<128, PITCH>(ins, Ws, accA, accB);

    int rr = tid >> 2;
    int q  = tid & 3;

    float4 oA[4], oB[4];
#pragma unroll
    for (int g = 0; g < 4; g++) {
        oA[g] = acc_relu4(accA[g * 2], accA[g * 2 + 1]);
        oB[g] = acc_relu4(accB[g * 2], accB[g * 2 + 1]);
    }

    if (!LAST) {
        if (node0 + rr < n) {
            float* Cr = &C[(size_t)(node0 + rr) * 64 + q * 4];
#pragma unroll
            for (int g = 0; g < 4; g++) *(float4*)&Cr[g * 16] = oA[g];
        }
        if (node0 + rr + 64 < n) {
            float* Cr = &C[(size_t)(node0 + rr + 64) * 64 + q * 4];
#pragma unroll
            for (int g = 0; g < 4; g++) *(float4*)&Cr[g * 16] = oB[g];
        }
    } else {
        // per-node dot with W_read[64:]
        float dA = 0.f, dB = 0.f;
#pragma unroll
        for (int g = 0; g < 4; g++) {
            const float* wv = &Wrs[g * 16 + q * 4];
            dA += oA[g].x * wv[0] + oA[g].y * wv[1] + oA[g].z * wv[2] + oA[g].w * wv[3];
            dB += oB[g].x * wv[0] + oB[g].y * wv[1] + oB[g].z * wv[2] + oB[g].w * wv[3];
        }
        dA += __shfl_xor_sync(0xffffffffu, dA, 1);
        dA += __shfl_xor_sync(0xffffffffu, dA, 2);
        dB += __shfl_xor_sync(0xffffffffu, dB, 1);
        dB += __shfl_xor_sync(0xffffffffu, dB, 2);
        if (q == 0) {
            if (node0 + rr < n)      out[node0 + rr]      = dA;
            if (node0 + rr + 64 < n) out[node0 + rr + 64] = dB;
        }
        // stash relu'd rows into ins for the segmented per-graph reduce
        __syncthreads();
#pragma unroll
        for (int g = 0; g < 4; g++) {
            *(float4*)&ins[rr * PITCH + g * 16 + q * 4]        = oA[g];
            *(float4*)&ins[(rr + 64) * PITCH + g * 16 + q * 4] = oB[g];
        }
        __syncthreads();
        if (tid < 64) {
            int c = tid;
            float acc = 0.f, cnt = 0.f;
            int curb = -1;
            for (int i = 0; i < 128; i++) {
                int node = node0 + i;
                if (node >= n) break;
                int b = __ldg(&batch[node]);
                if (b != curb) {
                    if (curb >= 0) {
                        atomicAdd(&g_means[curb * 64 + c], acc);
                        if (c == 0) atomicAdd(&g_cnt[curb], cnt);
                    }
                    acc = 0.f; cnt = 0.f; curb = b;
                }
                acc += ins[i * PITCH + c];
                cnt += 1.f;
            }
            if (curb >= 0) {
                atomicAdd(&g_means[curb * 64 + c], acc);
                if (c == 0) atomicAdd(&g_cnt[curb], cnt);
            }
        }
    }
}

// eemb = relu( nagg @ We2 ), K=64, 128 nodes / block
__global__ __launch_bounds__(256) void k_gemm64(const float* __restrict__ A,
                                                const float* __restrict__ W,
                                                float* __restrict__ C, int n) {
    extern __shared__ float sm[];
    const int PITCH = 68;
    float* Ws  = sm;               // 64*64
    float* ins = sm + 64 * 64;     // 128*68
    int tid = threadIdx.x;
    int node0 = blockIdx.x * 128;

    for (int idx = tid; idx < 64 * 16; idx += 256)
        ((float4*)Ws)[idx] = __ldg((const float4*)W + idx);
    for (int idx = tid; idx < 2048; idx += 256) {
        int r = idx >> 4, c4 = (idx & 15) << 2;
        int node = node0 + r;
        float4 va = (node < n) ? __ldg((const float4*)&A[(size_t)node * 64 + c4])
                               : make_float4(0.f, 0.f, 0.f, 0.f);
        *(float4*)&ins[r * PITCH + c4] = va;
    }
    __syncthreads();

    ull accA[8], accB[8];
    gemm_core2<64, PITCH>(ins, Ws, accA, accB);

    int rr = tid >> 2;
    int q  = tid & 3;
    if (node0 + rr < n) {
        float* Cr = &C[(size_t)(node0 + rr) * 64 + q * 4];
#pragma unroll
        for (int g = 0; g < 4; g++) *(float4*)&Cr[g * 16] = acc_relu4(accA[g * 2], accA[g * 2 + 1]);
    }
    if (node0 + rr + 64 < n) {
        float* Cr = &C[(size_t)(node0 + rr + 64) * 64 + q * 4];
#pragma unroll
        for (int g = 0; g < 4; g++) *(float4*)&Cr[g * 16] = acc_relu4(accB[g * 2], accB[g * 2 + 1]);
    }
}

// gconst[g] = relu(mean_g @ W_pool) . W_read[:64] + b_read
__global__ void k_gconst(const float* __restrict__ Wp, const float* __restrict__ Wr,
                         const float* __restrict__ br) {
    int g = blockIdx.x;
    int t = threadIdx.x;  // 64 threads
    __shared__ float m[64];
    __shared__ float red[64];
    float cnt = g_cnt[g];
    if (cnt <= 0.f) { if (t == 0) g_gconst[g] = 0.f; return; }
    m[t] = g_means[g * 64 + t] / cnt;
    __syncthreads();
    float p = 0.f;
#pragma unroll 8
    for (int k = 0; k < 64; k++) p += m[k] * __ldg(&Wp[k * 64 + t]);
    red[t] = fmaxf(p, 0.f) * __ldg(&Wr[t]);
    __syncthreads();
    if (t < 32) {
        float s = red[t] + red[t + 32];
#pragma unroll
        for (int off = 16; off > 0; off >>= 1) s += __shfl_down_sync(0xffffffffu, s, off);
        if (t == 0) g_gconst[g] = s + __ldg(&br[0]);
    }
}

// out[i] += gconst[batch[i]]
__global__ void k_addg(const int* __restrict__ batch, float* __restrict__ out, int n) {
    int i = blockIdx.x * blockDim.x + threadIdx.x;
    if (i < n) out[i] += g_gconst[__ldg(&batch[i])];
}

// ---------------------------------------------------------------------------
extern "C" void kernel_launch(void* const* d_in, const int* in_sizes, int n_in,
                              void* d_out, int out_size) {
    const float* x    = (const float*)d_in[0];
    const float* Wi   = (const float*)d_in[1];
    const float* We1  = (const float*)d_in[2];
    const float* We2  = (const float*)d_in[3];
    const float* Wmsg = (const float*)d_in[4];
    const float* Wupd = (const float*)d_in[5];
    const float* Wp   = (const float*)d_in[6];
    const float* Wr   = (const float*)d_in[7];
    const float* br   = (const float*)d_in[8];
    const int*   eidx = (const int*)d_in[9];
    const int*   batch= (const int*)d_in[10];

    int n    = in_sizes[10];
    int E    = in_sizes[9] / 2;
    int nobs = in_sizes[0] / n;
    int L    = in_sizes[4] / (128 * 64);
    const int* row = eidx;
    const int* col = eidx + E;
    float* out = (float*)d_out;

    float *curA, *curB, *hbuf, *nagg, *msg, *eemb, *means, *cnt;
    int* deg;
    cudaGetSymbolAddress((void**)&curA, g_curA);
    cudaGetSymbolAddress((void**)&curB, g_curB);
    cudaGetSymbolAddress((void**)&hbuf, g_h);
    cudaGetSymbolAddress((void**)&nagg, g_nagg);
    cudaGetSymbolAddress((void**)&msg,  g_msg);
    cudaGetSymbolAddress((void**)&eemb, g_eemb);
    cudaGetSymbolAddress((void**)&means, g_means);
    cudaGetSymbolAddress((void**)&cnt,   g_cnt);
    cudaGetSymbolAddress((void**)&deg,   g_deg);

    const int SMEM128 = (128 * 64 + 128 * 132) * 4;  // 100352
    const int SMEM64  = (64 * 64 + 128 * 68) * 4;    // 51200
    cudaFuncSetAttribute(k_gemm128<false>, cudaFuncAttributeMaxDynamicSharedMemorySize, SMEM128);
    cudaFuncSetAttribute(k_gemm128<true>,  cudaFuncAttributeMaxDynamicSharedMemorySize, SMEM128);
    cudaFuncSetAttribute(k_gemm64, cudaFuncAttributeMaxDynamicSharedMemorySize, SMEM64);

    int gE  = (E + 255) / 256;
    int gNF = (n * 64 + 255) / 256;
    int gHW = (n * 16 + 255) / 256;
    int gG  = (n + 127) / 128;
    int gA  = (n + 255) / 256;

    cudaMemsetAsync(deg,   0, (size_t)n * sizeof(int));
    cudaMemsetAsync(means, 0, (size_t)MAXG * FD * sizeof(float));
    cudaMemsetAsync(cnt,   0, (size_t)MAXG * sizeof(float));

    k_deg<<<gE, 256>>>(col, E);
    k_scan<<<1, 1024>>>(n);
    k_fill<<<gE, 256>>>(row, col, E);
    k_init<<<gNF, 256>>>(x, Wi, We1, n, nobs);

    // edge embedding
    k_gather<<<gHW, 256>>>(hbuf, nagg, n, 1);
    k_gemm64<<<gG, 256, SMEM64>>>(nagg, We2, eemb, n);

    float* cin = curA;
    float* cout = curB;
    for (int l = 0; l < L; l++) {
        bool last = (l == L - 1);
        k_gather<<<gHW, 256>>>(cin, nagg, n, 0);
        k_gemm128<false><<<gG, 256, SMEM128>>>(nagg, eemb, Wmsg + (size_t)l * 8192, msg,
                                               nullptr, nullptr, nullptr, n);
        if (!last) {
            k_gemm128<false><<<gG, 256, SMEM128>>>(cin, msg, Wupd + (size_t)l * 8192, cout,
                                                   nullptr, nullptr, nullptr, n);
            float* tmp = cin; cin = cout; cout = tmp;
        } else {
            k_gemm128<true><<<gG, 256, SMEM128>>>(cin, msg, Wupd + (size_t)l * 8192, nullptr,
                                                  Wr, batch, out, n);
        }
    }

    k_gconst<<<MAXG, 64>>>(Wp, Wr, br);
    k_addg<<<gA, 256>>>(batch, out, n);
}